// round 11
// baseline (speedup 1.0000x reference)
#include <cuda_runtime.h>
#include <cuda_bf16.h>
#include <cstdint>

// Problem constants (fixed by the dataset)
#define Tn 2000
#define Bn 64
#define Vn 163
#define Ln 200
#define Sn 401          // 2*L+1 extended states
#define NEGF (-1e30f)
#define CHK 14          // states per lane (even => j parity == state parity)
#define NOD 7           // odd (label) states per lane
#define DP  16          // prefetch depth (steps)
#define KMIN (-(1 << 29))

typedef unsigned long long u64;

// Packed per-(t,b) row: one uint4 (8 bf16) per lane, STRIDE-4 pair order:
// wd.x=(r0,r4) wd.y=(r1,r5) wd.z=(r2,r6) wd.w=(r3,0)
__device__ uint4 g_upk[Tn * Bn * 32];    // 65.5 MB
__device__ int   g_eo[Bn * 256];         // per-b gather indices [b][i*32+lane]
__device__ float g_adjsum[Bn];           // sum over t<act of (lse - logit_blank)
__device__ float g_partial[Bn];          // -(log pe') from alpha kernel

// ---- packed f32x2 helpers (Blackwell) ----
#define PK2(out, lo, hi)  asm("mov.b64 %0, {%1, %2};" : "=l"(out) : "r"(lo), "r"(hi))
#define UPK2(lo, hi, in)  asm("mov.b64 {%0, %1}, %2;" : "=r"(lo), "=r"(hi) : "l"(in))
#define FADD2(out, a, b)  asm("add.rn.f32x2 %0, %1, %2;" : "=l"(out) : "l"(a), "l"(b))
#define FMUL2(out, a, b)  asm("mul.rn.f32x2 %0, %1, %2;" : "=l"(out) : "l"(a), "l"(b))
#define FFMA2(out, a, b, c) asm("fma.rn.f32x2 %0, %1, %2, %3;" : "=l"(out) : "l"(a), "l"(b), "l"(c))

// ---------------------------------------------------------------------------
// Kernel 0: per-b gather-index table; zeroes adj accumulators (replay-safe).
// ---------------------------------------------------------------------------
__global__ void eo_kernel(const int* __restrict__ labels,
                          const int* __restrict__ label_lens) {
    int b = blockIdx.x, lane = threadIdx.x;
    if (lane == 0) g_adjsum[b] = 0.f;
    int smax = 2 * label_lens[b];
#pragma unroll
    for (int i = 0; i < NOD; i++) {
        int s  = lane * CHK + 2 * i + 1;
        int li = NOD * lane + i;               // (s-1)/2
        int ee = Vn;                           // sentinel -> r = exp(NEGF) = 0
        if (s < Sn && s <= smax) ee = labels[b * Ln + li];
        g_eo[(b << 8) + (i << 5) + lane] = ee;
    }
}

__device__ __forceinline__ uint32_t packbf(float a, float bx) {
    __nv_bfloat162 h = __floats2bfloat162_rn(a, bx);   // x=a(lo), y=bx(hi)
    return *reinterpret_cast<uint32_t*>(&h);
}

// ---------------------------------------------------------------------------
// Kernel 1: one warp per (t,b) row. Raw logits -> warp smem; emits
// bf16-packed ratio pairs (stride-4 order); accumulates adj into g_adjsum[b].
// ---------------------------------------------------------------------------
__global__ __launch_bounds__(256) void prep_kernel(const float* __restrict__ logits,
                                                   const int* __restrict__ act_lens) {
    __shared__ float us[8][164];   // raw logit row; [163] == NEGF sentinel

    int row = blockIdx.x * 8 + (threadIdx.x >> 5);   // row = t*Bn + b
    if (row >= Tn * Bn) return;
    int lane = threadIdx.x & 31;
    int w    = threadIdx.x >> 5;
    int b    = row & (Bn - 1);
    int t    = row >> 6;
    const float* p = logits + (size_t)row * Vn;

    float v[6];
    float m = NEGF;
#pragma unroll
    for (int k = 0; k < 6; k++) {
        int i = lane + 32 * k;
        v[k] = (i < Vn) ? p[i] : NEGF;
        m = fmaxf(m, v[k]);
        if (i < 164) us[w][i] = v[k];          // i==163 stays NEGF
    }
    __syncwarp();

    float blank = us[w][0];

    float r[NOD];
#pragma unroll
    for (int i = 0; i < NOD; i++)
        r[i] = __expf(us[w][g_eo[(b << 8) + (i << 5) + lane]] - blank);

    uint4 wd;
    wd.x = packbf(r[0], r[4]);
    wd.y = packbf(r[1], r[5]);
    wd.z = packbf(r[2], r[6]);
    wd.w = packbf(r[3], 0.f);
    g_upk[(size_t)row * 32 + lane] = wd;

    // lse reduction -> adj = lse - blank; accumulate if t < act
#pragma unroll
    for (int off = 16; off; off >>= 1) m = fmaxf(m, __shfl_xor_sync(0xffffffffu, m, off));
    float sum = 0.f;
#pragma unroll
    for (int k = 0; k < 6; k++) sum += __expf(v[k] - m);
#pragma unroll
    for (int off = 16; off; off >>= 1) sum += __shfl_xor_sync(0xffffffffu, sum, off);
    if (lane == 0 && t < act_lens[b])
        atomicAdd(&g_adjsum[b], m + __logf(sum) - blank);
}

// term aligned to kmax: keep (d==0), downshift one 64-bit unit (d==-1), else 0
__device__ __forceinline__ float termf(float m, int d) {
    return (d == 0) ? m : ((d == -1) ? m * 0x1p-64f : 0.f);
}

// ---------------------------------------------------------------------------
// Kernel 2: CTC alpha (blank-factored), one warp per batch, f32x2 packed.
// State: PE[i]=(E[i],E[i+4]), PO[i]=(O[i],O[i+4]); value = x * 2^(64*kk).
// Per step: 1 LDG.128, 1 shuffle, 16 f32x2 fma-pipe ops, ~14 alu.
// Exponent logic at 4-step group boundaries, branchless.
// ---------------------------------------------------------------------------
#define SCALE_ALL(FO_) do {                                                    \
    FMUL2(PE0, PE0, FO_); FMUL2(PE1, PE1, FO_);                                \
    FMUL2(PE2, PE2, FO_); FMUL2(PE3, PE3, FO_);                                \
    FMUL2(PO0, PO0, FO_); FMUL2(PO1, PO1, FO_);                                \
    FMUL2(PO2, PO2, FO_); FMUL2(PO3, PO3, FO_);                                \
} while (0)

#define PREAMBLE() do {                                                        \
    int nk = __shfl_up_sync(0xffffffffu, kk, 1);                               \
    if (lane == 0) nk = kk;                                                    \
    int d = nk - kk;                                                           \
    float fo = (d <= 0) ? 1.f : ((d == 1) ? 0x1p-64f : 0.f);                   \
    u64 FO; uint32_t fb = __float_as_uint(fo); PK2(FO, fb, fb);                \
    SCALE_ALL(FO);                                                             \
    kk = (d > 0) ? nk : kk;                                                    \
    sc = (d >= 0) ? 1.f : ((d == -1) ? 0x1p-64f : 0.f);                        \
} while (0)

#define RENORM() do {                                                          \
    uint32_t a0,a1,a2,a3,a4,a5,a6,a7;                                          \
    UPK2(a0, a1, PE0); UPK2(a2, a3, PE1);                                      \
    UPK2(a4, a5, PE2); UPK2(a6, a7, PE3);                                      \
    float mx = fmaxf(fmaxf(fmaxf(__uint_as_float(a0), __uint_as_float(a1)),    \
                           fmaxf(__uint_as_float(a2), __uint_as_float(a3))),   \
                     fmaxf(fmaxf(__uint_as_float(a4), __uint_as_float(a5)),    \
                           __uint_as_float(a6)));                              \
    int ov = (mx >= 0x1p40f) ? 1 : 0;                                          \
    float f = ov ? 0x1p-64f : 1.f;                                             \
    u64 FO; uint32_t fb = __float_as_uint(f); PK2(FO, fb, fb);                 \
    SCALE_ALL(FO);                                                             \
    kk += ov;                                                                  \
} while (0)

#define BODY(T_, Q_) do {                                                      \
    uint32_t o6b, o5b, o3b, jnk;                                               \
    UPK2(o5b, o6b, PO2);            /* (O5, O6); O6 = m13 */                   \
    UPK2(o3b, jnk, PO3);            /* (O3, junk) */                           \
    float nm = __shfl_up_sync(0xffffffffu, __uint_as_float(o6b), 1);           \
    if (lane == 0) nm = 0.f;                                                   \
    nm *= sc;                                                                  \
    uint4 wv = buf[Q_];                                                        \
    u64 R0, R1, R2, R3, OP0;                                                   \
    PK2(R0, wv.x << 16, wv.x & 0xFFFF0000u);                                   \
    PK2(R1, wv.y << 16, wv.y & 0xFFFF0000u);                                   \
    PK2(R2, wv.z << 16, wv.z & 0xFFFF0000u);                                   \
    PK2(R3, wv.w << 16, wv.w & 0xFFFF0000u);                                   \
    PK2(OP0, __float_as_uint(nm), o3b);   /* (nm, O3) */                       \
    u64 nPE0, nPE1, nPE2, nPE3, t0_, t1_, t2_, t3_, s0_, s1_, s2_, s3_;        \
    FADD2(nPE0, PE0, OP0);                                                     \
    FADD2(nPE1, PE1, PO0);                                                     \
    FADD2(nPE2, PE2, PO1);                                                     \
    FADD2(nPE3, PE3, PO2);                                                     \
    FFMA2(t0_, AL0, OP0, PE0); FADD2(s0_, PO0, t0_);                           \
    FFMA2(t1_, AL1, PO0, PE1); FADD2(s1_, PO1, t1_);                           \
    FFMA2(t2_, AL2, PO1, PE2); FADD2(s2_, PO2, t2_);                           \
    FFMA2(t3_, AL3, PO2, PE3); FADD2(s3_, PO3, t3_);                           \
    FMUL2(PO0, s0_, R0); FMUL2(PO1, s1_, R1);                                  \
    FMUL2(PO2, s2_, R2); FMUL2(PO3, s3_, R3);                                  \
    PE0 = nPE0; PE1 = nPE1; PE2 = nPE2; PE3 = nPE3;                            \
    int tp = (T_) + DP; if (tp > Tn - 1) tp = Tn - 1;                          \
    buf[Q_] = __ldg(g_upk + ((size_t)tp * Bn + b) * 32 + lane);                \
} while (0)

#define GROUP4(TB_, QB_) do {                                                  \
    PREAMBLE();                                                                \
    BODY((TB_) + 0, (QB_) + 0); BODY((TB_) + 1, (QB_) + 1);                    \
    BODY((TB_) + 2, (QB_) + 2); BODY((TB_) + 3, (QB_) + 3);                    \
    RENORM();                                                                  \
} while (0)

__global__ __launch_bounds__(32, 1) void ctc_alpha_kernel(
    const int* __restrict__ labels,
    const int* __restrict__ act_lens,
    const int* __restrict__ label_lens)
{
    const int b    = blockIdx.x;
    const int lane = threadIdx.x;
    const int act  = act_lens[b];
    const int lab  = label_lens[b];
    const int smax = 2 * lab;            // final blank state (lab >= 100)

    // skip-allowed flags for this lane's odd states, packed stride-4
    float al[NOD + 1];
#pragma unroll
    for (int i = 0; i < NOD; i++) {
        int s  = lane * CHK + 2 * i + 1;
        int li = NOD * lane + i;
        float af = 0.f;
        if (s >= 3 && s < Sn && s <= smax)
            af = (labels[b * Ln + li] != labels[b * Ln + li - 1]) ? 1.f : 0.f;
        al[i] = af;
    }
    al[NOD] = 0.f;                       // junk slot
    u64 AL0, AL1, AL2, AL3;
    PK2(AL0, __float_as_uint(al[0]), __float_as_uint(al[4]));
    PK2(AL1, __float_as_uint(al[1]), __float_as_uint(al[5]));
    PK2(AL2, __float_as_uint(al[2]), __float_as_uint(al[6]));
    PK2(AL3, __float_as_uint(al[3]), __float_as_uint(al[7]));

    // t = 0 init: m[0] = 1 (E0, lane 0), m[1] = r0(t=0) (O0, lane 0)
    u64 PE0 = 0, PE1 = 0, PE2 = 0, PE3 = 0;
    u64 PO0 = 0, PO1 = 0, PO2 = 0, PO3 = 0;
    {
        uint4 w0 = __ldg(g_upk + (size_t)b * 32 + lane);
        if (lane == 0) {
            PK2(PE0, 0x3f800000u, 0u);          // (1.0, 0)
            PK2(PO0, w0.x << 16, 0u);           // (r0, 0)
        }
    }
    int   kk = 0;
    float sc = 1.f;

    // prologue: slot q holds row 1+q
    uint4 buf[DP];
#pragma unroll
    for (int q = 0; q < DP; q++)
        buf[q] = __ldg(g_upk + ((size_t)(1 + q) * Bn + b) * 32 + lane);

    int t0 = 1;
    for (; t0 + DP - 1 < act; t0 += DP) {    // act >= 1000 always
        GROUP4(t0,      0);
        GROUP4(t0 + 4,  4);
        GROUP4(t0 + 8,  8);
        GROUP4(t0 + 12, 12);
    }
#pragma unroll
    for (int q = 0; q < DP - 1; q++) {
        if (t0 + q < act) { PREAMBLE(); BODY(t0 + q, q); RENORM(); }
    }

    // publish final alphas (unpack state) and combine
    __shared__ float2 fin[32 * CHK];
    {
        uint32_t e0,e4,e1,e5,e2,e6,e3,ej, o0,o4,o1,o5,o2,o6,o3,oj;
        UPK2(e0, e4, PE0); UPK2(e1, e5, PE1); UPK2(e2, e6, PE2); UPK2(e3, ej, PE3);
        UPK2(o0, o4, PO0); UPK2(o1, o5, PO1); UPK2(o2, o6, PO2); UPK2(o3, oj, PO3);
        float kf = __int_as_float(kk);
        fin[lane*CHK +  0] = make_float2(__uint_as_float(e0), kf);
        fin[lane*CHK +  1] = make_float2(__uint_as_float(o0), kf);
        fin[lane*CHK +  2] = make_float2(__uint_as_float(e1), kf);
        fin[lane*CHK +  3] = make_float2(__uint_as_float(o1), kf);
        fin[lane*CHK +  4] = make_float2(__uint_as_float(e2), kf);
        fin[lane*CHK +  5] = make_float2(__uint_as_float(o2), kf);
        fin[lane*CHK +  6] = make_float2(__uint_as_float(e3), kf);
        fin[lane*CHK +  7] = make_float2(__uint_as_float(o3), kf);
        fin[lane*CHK +  8] = make_float2(__uint_as_float(e4), kf);
        fin[lane*CHK +  9] = make_float2(__uint_as_float(o4), kf);
        fin[lane*CHK + 10] = make_float2(__uint_as_float(e5), kf);
        fin[lane*CHK + 11] = make_float2(__uint_as_float(o5), kf);
        fin[lane*CHK + 12] = make_float2(__uint_as_float(e6), kf);
        fin[lane*CHK + 13] = make_float2(__uint_as_float(o6), kf);
    }
    __syncwarp();

    if (lane == 0) {
        float2 ve = fin[smax], vp2 = fin[smax - 1];
        int ke = (ve.x  > 0.f) ? __float_as_int(ve.y)  : KMIN;
        int kp = (vp2.x > 0.f) ? __float_as_int(vp2.y) : KMIN;
        int km = max(ke, kp);
        float pe = termf(ve.x, ke - km) + termf(vp2.x, kp - km);
        double ll;
        if (km == KMIN || pe <= 0.f) ll = -1e30;   // unreachable in practice
        else ll = log((double)pe) + (double)km * (64.0 * 0.6931471805599453);
        g_partial[b] = (float)(-ll);               // final adds +g_adjsum[b]
    }
}

// ---------------------------------------------------------------------------
// Kernel 3: total = sum_b(partial + adjsum) / sum(act_lens). 64 threads.
// ---------------------------------------------------------------------------
__global__ void final_kernel(const int* __restrict__ act_lens,
                             float* __restrict__ out)
{
    int tid = threadIdx.x;  // 64 threads
    double l = (double)g_partial[tid] + (double)g_adjsum[tid];
    double a = (double)act_lens[tid];
#pragma unroll
    for (int o = 16; o; o >>= 1) {
        l += __shfl_xor_sync(0xffffffffu, l, o);
        a += __shfl_xor_sync(0xffffffffu, a, o);
    }
    __shared__ double sl[2], sa[2];
    if ((tid & 31) == 0) { sl[tid >> 5] = l; sa[tid >> 5] = a; }
    __syncthreads();
    if (tid == 0) out[0] = (float)((sl[0] + sl[1]) / (sa[0] + sa[1]));
}

// ---------------------------------------------------------------------------
extern "C" void kernel_launch(void* const* d_in, const int* in_sizes, int n_in,
                              void* d_out, int out_size)
{
    const float* logits     = (const float*)d_in[0];  // [T, B, V]
    const int*   labels     = (const int*)d_in[1];    // [B, L]
    const int*   act_lens   = (const int*)d_in[2];    // [B]
    const int*   label_lens = (const int*)d_in[3];    // [B]

    eo_kernel<<<Bn, 32>>>(labels, label_lens);
    prep_kernel<<<(Tn * Bn + 7) / 8, 256>>>(logits, act_lens);
    ctc_alpha_kernel<<<Bn, 32>>>(labels, act_lens, label_lens);
    final_kernel<<<1, 64>>>(act_lens, (float*)d_out);
}